// round 16
// baseline (speedup 1.0000x reference)
#include <cuda_runtime.h>
#include <cuda_fp16.h>
#include <cstdint>

// Deformable Conv2d: B=8, C=3, H=W=512, O=16, K=3, PAD=1.
// R16 = R13 (best: vertical-pair 16B image, streaming hints, f32x2 const
// contraction, launch_bounds(256,4)) with the ENTIRE bilinear lerp in fp16
// half2 (x and y), converting only the 3 final s-values to fp32.

#define Bn 8
#define Cc 3
#define Hh 512
#define Ww 512
#define Oo 16
#define KK 9
#define HW (Hh * Ww)

#define PROWS 514            // row index yy = y0+1, y0 in [-1,512]
#define PSTRIDE 516
#define PTOT (PROWS * PSTRIDE)

#define NW (KK * Cc * 8)     // 216 packed weight pairs
#define NC (NW + 8)          // + 8 packed bias pairs

__device__ uint4 g_xp[Bn * PTOT];            // vertical-pair fp16 image (~34MB)
__device__ unsigned long long g_stage[NC];

__constant__ unsigned long long cst[NC];

__device__ __forceinline__ unsigned long long pack_pair(float a, float b)
{
    unsigned long long u;
    asm("mov.b64 %0, {%1, %2};" : "=l"(u) : "f"(a), "f"(b));
    return u;
}
__device__ __forceinline__ unsigned long long pack2(float v)
{
    unsigned long long u;
    asm("mov.b64 %0, {%1, %1};" : "=l"(u) : "f"(v));
    return u;
}
__device__ __forceinline__ __half2 asH2(uint32_t u)
{
    return *reinterpret_cast<__half2*>(&u);
}
__device__ __forceinline__ float ldg_stream(const float* p)
{
    float v;
    asm volatile("ld.global.nc.cs.f32 %0, [%1];" : "=f"(v) : "l"(p));
    return v;
}
__device__ __forceinline__ void stg_stream(float* p, float v)
{
    asm volatile("st.global.cs.f32 [%0], %1;" :: "l"(p), "f"(v) : "memory");
}

// ---------------- repack + weight prep ----------------
__global__ __launch_bounds__(256) void repack_kernel(
    const float* __restrict__ x,
    const float* __restrict__ weight,
    const float* __restrict__ bias)
{
    if (blockIdx.x == 0) {
        int i = threadIdx.x;
        if (i < NW) {
            int k = i / (Cc * 8);
            int r = i % (Cc * 8);
            int c = r / 8;
            int j = r % 8;
            float w0 = weight[(2 * j + 0) * (Cc * KK) + c * KK + k];
            float w1 = weight[(2 * j + 1) * (Cc * KK) + c * KK + k];
            g_stage[i] = pack_pair(w0, w1);
        } else if (i < NC) {
            int j = i - NW;
            g_stage[i] = pack_pair(bias[2 * j], bias[2 * j + 1]);
        }
    }

    int i = blockIdx.x * 256 + threadIdx.x;
    if (i >= Bn * PTOT) return;
    int b = i / PTOT;
    int p = i % PTOT;
    int yy = p / PSTRIDE;
    int xx = p % PSTRIDE;

    // top row = yy-1, bottom row = yy (image coords), col = xx-1
    uint4 u = make_uint4(0u, 0u, 0u, 0u);
    bool cx = (xx >= 1) && (xx <= Ww);
    if (cx) {
        const float* xb = x + (size_t)b * Cc * HW + (xx - 1);
        if (yy >= 1 && yy <= Hh) {
            const float* pt = xb + (size_t)(yy - 1) * Ww;
            __half2 h01 = __floats2half2_rn(pt[0], pt[HW]);
            __half2 h23 = __floats2half2_rn(pt[2 * HW], 0.0f);
            u.x = *reinterpret_cast<unsigned int*>(&h01);
            u.y = *reinterpret_cast<unsigned int*>(&h23);
        }
        if (yy < Hh) {
            const float* pb = xb + (size_t)yy * Ww;
            __half2 h01 = __floats2half2_rn(pb[0], pb[HW]);
            __half2 h23 = __floats2half2_rn(pb[2 * HW], 0.0f);
            u.z = *reinterpret_cast<unsigned int*>(&h01);
            u.w = *reinterpret_cast<unsigned int*>(&h23);
        }
    }
    g_xp[i] = u;
}

// ---------------- main kernel ----------------
__global__ __launch_bounds__(256, 4) void dcn_kernel(
    const float* __restrict__ off,
    float* __restrict__ out)
{
    int idx = blockIdx.x * 256 + threadIdx.x;    // exact grid
    int w = idx & (Ww - 1);
    int h = (idx >> 9) & (Hh - 1);
    int b = idx >> 18;

    const uint4* xtb = g_xp + (size_t)b * PTOT;
    const float* ob = off + (size_t)b * (2 * KK) * HW + (size_t)h * Ww + w;

    const float hf = (float)h;
    const float wf = (float)w;

    unsigned long long accp[8];
#pragma unroll
    for (int j = 0; j < 8; j++) accp[j] = cst[NW + j];

#pragma unroll
    for (int k = 0; k < KK; k++) {
        const int ky = k / 3;
        const int kx = k % 3;
        float dy = ldg_stream(ob + (size_t)(2 * k) * HW);
        float dx = ldg_stream(ob + (size_t)(2 * k + 1) * HW);

        float py = dy + (hf + (float)(ky - 1));
        float px = dx + (wf + (float)(kx - 1));

        py = fminf(fmaxf(py, -1.0f), 512.0f);
        px = fminf(fmaxf(px, -1.0f), 512.0f);

        float y0f = floorf(py);
        float x0f = floorf(px);
        float fy = py - y0f;
        float fx = px - x0f;
        int y0 = (int)y0f;
        int x0 = (int)x0f;

        int base = (y0 + 1) * PSTRIDE + (x0 + 1);

        uint4 uL = __ldg(xtb + base);       // {top c01, top c2-, bot c01, bot c2-} at x0
        uint4 uR = __ldg(xtb + base + 1);   // same at x0+1

        // ---- full fp16 bilinear: x-lerp then y-lerp in half2 ----
        __half2 fx2 = __float2half2_rn(fx);
        __half2 fy2 = __float2half2_rn(fy);
        __half2 t01 = __hfma2(fx2, __hsub2(asH2(uR.x), asH2(uL.x)), asH2(uL.x));
        __half2 t2  = __hfma2(fx2, __hsub2(asH2(uR.y), asH2(uL.y)), asH2(uL.y));
        __half2 b01 = __hfma2(fx2, __hsub2(asH2(uR.z), asH2(uL.z)), asH2(uL.z));
        __half2 b2  = __hfma2(fx2, __hsub2(asH2(uR.w), asH2(uL.w)), asH2(uL.w));

        __half2 s01h = __hfma2(fy2, __hsub2(b01, t01), t01);
        __half2 s2h  = __hfma2(fy2, __hsub2(b2, t2), t2);

        float2 s01 = __half22float2(s01h);
        float  s2  = __low2float(s2h);

        unsigned long long sp0 = pack2(s01.x);
        unsigned long long sp1 = pack2(s01.y);
        unsigned long long sp2 = pack2(s2);

#pragma unroll
        for (int j = 0; j < 8; j++) {
            asm("fma.rn.f32x2 %0, %1, %2, %0;"
                : "+l"(accp[j]) : "l"(sp0), "l"(cst[(k * Cc + 0) * 8 + j]));
            asm("fma.rn.f32x2 %0, %1, %2, %0;"
                : "+l"(accp[j]) : "l"(sp1), "l"(cst[(k * Cc + 1) * 8 + j]));
            asm("fma.rn.f32x2 %0, %1, %2, %0;"
                : "+l"(accp[j]) : "l"(sp2), "l"(cst[(k * Cc + 2) * 8 + j]));
        }
    }

    float* ot = out + (size_t)b * Oo * HW + (size_t)h * Ww + w;
#pragma unroll
    for (int j = 0; j < 8; j++) {
        float lo, hi;
        asm("mov.b64 {%0, %1}, %2;" : "=f"(lo), "=f"(hi) : "l"(accp[j]));
        stg_stream(ot + (size_t)(2 * j + 0) * HW, lo);
        stg_stream(ot + (size_t)(2 * j + 1) * HW, hi);
    }
}

extern "C" void kernel_launch(void* const* d_in, const int* in_sizes, int n_in,
                              void* d_out, int out_size)
{
    const float* x      = (const float*)d_in[0];
    const float* off    = (const float*)d_in[1];
    const float* weight = (const float*)d_in[2];
    const float* bias   = (const float*)d_in[3];
    float* out          = (float*)d_out;

    int ptotal = Bn * PTOT;
    repack_kernel<<<(ptotal + 255) / 256, 256>>>(x, weight, bias);

    void* src = nullptr;
    cudaGetSymbolAddress(&src, g_stage);
    cudaMemcpyToSymbolAsync(cst, src, NC * sizeof(unsigned long long),
                            0, cudaMemcpyDeviceToDevice);

    int total = Bn * HW;                 // 2,097,152
    dcn_kernel<<<total / 256, 256>>>(off, out);
}

// round 17
// speedup vs baseline: 1.0472x; 1.0472x over previous
#include <cuda_runtime.h>
#include <cuda_fp16.h>
#include <cstdint>

// Deformable Conv2d: B=8, C=3, H=W=512, O=16, K=3, PAD=1.
// R17 = R13 (best config: vertical-pair 16B image, streaming hints on
// offsets/output, f32x2 const contraction, fp16 x-lerp + fp32 y-lerp)
// with an occupancy push: __launch_bounds__(128, 9) -> 56-reg budget,
// 36 warps/SM to saturate the L1 wavefront pipe (dcn is L1-wf bound).

#define Bn 8
#define Cc 3
#define Hh 512
#define Ww 512
#define Oo 16
#define KK 9
#define HW (Hh * Ww)

#define PROWS 514            // row index yy = y0+1, y0 in [-1,512]
#define PSTRIDE 516
#define PTOT (PROWS * PSTRIDE)

#define NW (KK * Cc * 8)     // 216 packed weight pairs
#define NC (NW + 8)          // + 8 packed bias pairs

__device__ uint4 g_xp[Bn * PTOT];            // vertical-pair fp16 image (~34MB)
__device__ unsigned long long g_stage[NC];

__constant__ unsigned long long cst[NC];

__device__ __forceinline__ unsigned long long pack_pair(float a, float b)
{
    unsigned long long u;
    asm("mov.b64 %0, {%1, %2};" : "=l"(u) : "f"(a), "f"(b));
    return u;
}
__device__ __forceinline__ unsigned long long pack2(float v)
{
    unsigned long long u;
    asm("mov.b64 %0, {%1, %1};" : "=l"(u) : "f"(v));
    return u;
}
__device__ __forceinline__ __half2 asH2(uint32_t u)
{
    return *reinterpret_cast<__half2*>(&u);
}
__device__ __forceinline__ float ldg_stream(const float* p)
{
    float v;
    asm volatile("ld.global.nc.cs.f32 %0, [%1];" : "=f"(v) : "l"(p));
    return v;
}
__device__ __forceinline__ void stg_stream(float* p, float v)
{
    asm volatile("st.global.cs.f32 [%0], %1;" :: "l"(p), "f"(v) : "memory");
}

// ---------------- repack + weight prep ----------------
__global__ __launch_bounds__(256) void repack_kernel(
    const float* __restrict__ x,
    const float* __restrict__ weight,
    const float* __restrict__ bias)
{
    if (blockIdx.x == 0) {
        int i = threadIdx.x;
        if (i < NW) {
            int k = i / (Cc * 8);
            int r = i % (Cc * 8);
            int c = r / 8;
            int j = r % 8;
            float w0 = weight[(2 * j + 0) * (Cc * KK) + c * KK + k];
            float w1 = weight[(2 * j + 1) * (Cc * KK) + c * KK + k];
            g_stage[i] = pack_pair(w0, w1);
        } else if (i < NC) {
            int j = i - NW;
            g_stage[i] = pack_pair(bias[2 * j], bias[2 * j + 1]);
        }
    }

    int i = blockIdx.x * 256 + threadIdx.x;
    if (i >= Bn * PTOT) return;
    int b = i / PTOT;
    int p = i % PTOT;
    int yy = p / PSTRIDE;
    int xx = p % PSTRIDE;

    // top row = yy-1, bottom row = yy (image coords), col = xx-1
    uint4 u = make_uint4(0u, 0u, 0u, 0u);
    bool cx = (xx >= 1) && (xx <= Ww);
    if (cx) {
        const float* xb = x + (size_t)b * Cc * HW + (xx - 1);
        if (yy >= 1 && yy <= Hh) {
            const float* pt = xb + (size_t)(yy - 1) * Ww;
            __half2 h01 = __floats2half2_rn(pt[0], pt[HW]);
            __half2 h23 = __floats2half2_rn(pt[2 * HW], 0.0f);
            u.x = *reinterpret_cast<unsigned int*>(&h01);
            u.y = *reinterpret_cast<unsigned int*>(&h23);
        }
        if (yy < Hh) {
            const float* pb = xb + (size_t)yy * Ww;
            __half2 h01 = __floats2half2_rn(pb[0], pb[HW]);
            __half2 h23 = __floats2half2_rn(pb[2 * HW], 0.0f);
            u.z = *reinterpret_cast<unsigned int*>(&h01);
            u.w = *reinterpret_cast<unsigned int*>(&h23);
        }
    }
    g_xp[i] = u;
}

// ---------------- main kernel ----------------
__global__ __launch_bounds__(128, 9) void dcn_kernel(
    const float* __restrict__ off,
    float* __restrict__ out)
{
    int idx = blockIdx.x * 128 + threadIdx.x;    // exact grid
    int w = idx & (Ww - 1);
    int h = (idx >> 9) & (Hh - 1);
    int b = idx >> 18;

    const uint4* xtb = g_xp + (size_t)b * PTOT;
    const float* ob = off + (size_t)b * (2 * KK) * HW + (size_t)h * Ww + w;

    const float hf = (float)h;
    const float wf = (float)w;

    unsigned long long accp[8];
#pragma unroll
    for (int j = 0; j < 8; j++) accp[j] = cst[NW + j];

#pragma unroll
    for (int k = 0; k < KK; k++) {
        const int ky = k / 3;
        const int kx = k % 3;
        float dy = ldg_stream(ob + (size_t)(2 * k) * HW);
        float dx = ldg_stream(ob + (size_t)(2 * k + 1) * HW);

        float py = dy + (hf + (float)(ky - 1));
        float px = dx + (wf + (float)(kx - 1));

        py = fminf(fmaxf(py, -1.0f), 512.0f);
        px = fminf(fmaxf(px, -1.0f), 512.0f);

        float y0f = floorf(py);
        float x0f = floorf(px);
        float fy = py - y0f;
        float fx = px - x0f;
        int y0 = (int)y0f;
        int x0 = (int)x0f;

        int base = (y0 + 1) * PSTRIDE + (x0 + 1);

        uint4 uL = __ldg(xtb + base);       // {top c01, top c2-, bot c01, bot c2-} at x0
        uint4 uR = __ldg(xtb + base + 1);   // same at x0+1

        // ---- x-lerp in fp16, y-lerp in fp32 ----
        __half2 fx2 = __float2half2_rn(fx);
        __half2 t01 = __hfma2(fx2, __hsub2(asH2(uR.x), asH2(uL.x)), asH2(uL.x));
        __half2 t2  = __hfma2(fx2, __hsub2(asH2(uR.y), asH2(uL.y)), asH2(uL.y));
        __half2 b01 = __hfma2(fx2, __hsub2(asH2(uR.z), asH2(uL.z)), asH2(uL.z));
        __half2 b2  = __hfma2(fx2, __hsub2(asH2(uR.w), asH2(uL.w)), asH2(uL.w));

        float2 tf01 = __half22float2(t01);
        float2 bf01 = __half22float2(b01);
        float  tf2  = __low2float(t2);
        float  bf2  = __low2float(b2);

        float s0 = fmaf(fy, bf01.x - tf01.x, tf01.x);
        float s1 = fmaf(fy, bf01.y - tf01.y, tf01.y);
        float s2 = fmaf(fy, bf2 - tf2, tf2);

        unsigned long long sp0 = pack2(s0);
        unsigned long long sp1 = pack2(s1);
        unsigned long long sp2 = pack2(s2);

#pragma unroll
        for (int j = 0; j < 8; j++) {
            asm("fma.rn.f32x2 %0, %1, %2, %0;"
                : "+l"(accp[j]) : "l"(sp0), "l"(cst[(k * Cc + 0) * 8 + j]));
            asm("fma.rn.f32x2 %0, %1, %2, %0;"
                : "+l"(accp[j]) : "l"(sp1), "l"(cst[(k * Cc + 1) * 8 + j]));
            asm("fma.rn.f32x2 %0, %1, %2, %0;"
                : "+l"(accp[j]) : "l"(sp2), "l"(cst[(k * Cc + 2) * 8 + j]));
        }
    }

    float* ot = out + (size_t)b * Oo * HW + (size_t)h * Ww + w;
#pragma unroll
    for (int j = 0; j < 8; j++) {
        float lo, hi;
        asm("mov.b64 {%0, %1}, %2;" : "=f"(lo), "=f"(hi) : "l"(accp[j]));
        stg_stream(ot + (size_t)(2 * j + 0) * HW, lo);
        stg_stream(ot + (size_t)(2 * j + 1) * HW, hi);
    }
}

extern "C" void kernel_launch(void* const* d_in, const int* in_sizes, int n_in,
                              void* d_out, int out_size)
{
    const float* x      = (const float*)d_in[0];
    const float* off    = (const float*)d_in[1];
    const float* weight = (const float*)d_in[2];
    const float* bias   = (const float*)d_in[3];
    float* out          = (float*)d_out;

    int ptotal = Bn * PTOT;
    repack_kernel<<<(ptotal + 255) / 256, 256>>>(x, weight, bias);

    void* src = nullptr;
    cudaGetSymbolAddress(&src, g_stage);
    cudaMemcpyToSymbolAsync(cst, src, NC * sizeof(unsigned long long),
                            0, cudaMemcpyDeviceToDevice);

    int total = Bn * HW;                 // 2,097,152
    dcn_kernel<<<total / 128, 128>>>(off, out);
}